// round 6
// baseline (speedup 1.0000x reference)
#include <cuda_runtime.h>

// OWA pooling: 3x3 window, stride 2, SAME pad (0 top/left, 1 bottom/right),
// sort window descending, dot with per-channel rank weights.
// inputs: (16,224,224,64) f32 NHWC ; kernel: (9,64) f32 ; out: (16,112,112,64) f32

#define B_  16
#define H_  224
#define W_  224
#define C_  64
#define OH_ 112
#define OW_ 112
#define OW_PER_WARP 14   // 112 / 8 warps
#define ROWS_PER_CTA 2   // vertical L1 reuse: row r0+2 of pass 0 is r0 of pass 1

// Descending compare-exchange, FMNMX form (alu pipe): 4 ops per float2
#define CE(i, j)                                          \
    {                                                     \
        float tx = fmaxf(v[i].x, v[j].x);                 \
        float ty = fmaxf(v[i].y, v[j].y);                 \
        v[j].x = fminf(v[i].x, v[j].x);                   \
        v[j].y = fminf(v[i].y, v[j].y);                   \
        v[i].x = tx;                                      \
        v[i].y = ty;                                      \
    }

// Descending compare-exchange, arithmetic form (fma pipe):
// max = 0.5*((a+b)+|a-b|), min = 0.5*((a+b)-|a-b|).
#define CEF(i, j)                                         \
    {                                                     \
        float sx = v[i].x + v[j].x;                       \
        float dx = v[i].x - v[j].x;                       \
        float sy = v[i].y + v[j].y;                       \
        float dy = v[i].y - v[j].y;                       \
        float mxx = sx + fabsf(dx);                       \
        float mnx = sx - fabsf(dx);                       \
        float mxy = sy + fabsf(dy);                       \
        float mny = sy - fabsf(dy);                       \
        v[i].x = 0.5f * mxx;                              \
        v[j].x = 0.5f * mnx;                              \
        v[i].y = 0.5f * mxy;                              \
        v[j].y = 0.5f * mny;                              \
    }

__device__ __forceinline__ void l2_prefetch(const float* p) {
    asm volatile("prefetch.global.L2 [%0];" :: "l"(p));
}

__global__ __launch_bounds__(256, 3) void owa_pool_kernel(
    const float* __restrict__ in,   // (B,H,W,C)
    const float* __restrict__ kw,   // (9,C)
    float* __restrict__ out)        // (B,OH,OW,C)
{
    const int oh_base = blockIdx.x * ROWS_PER_CTA;
    const int b    = blockIdx.y;
    const int warp = threadIdx.x >> 5;
    const int lane = threadIdx.x & 31;
    const int c    = lane * 2;          // this thread's channel pair

    // Per-rank weights for this channel pair (loop-invariant)
    float2 wgt[9];
#pragma unroll
    for (int k = 0; k < 9; k++)
        wgt[k] = *reinterpret_cast<const float2*>(kw + k * C_ + c);

    const int ow0 = warp * OW_PER_WARP;

#pragma unroll 1
    for (int r = 0; r < ROWS_PER_CTA; ++r) {
        const int oh = oh_base + r;
        const int r0 = oh * 2;
        const bool r2ok = (r0 + 2 < H_);    // bottom pad row when oh == 111
        const float* base = in + ((b * H_ + r0) * W_) * C_ + c;

        auto loadcol = [&](int col, float2* dst) {
            if (col < W_) {
                dst[0] = *reinterpret_cast<const float2*>(base + col * C_);
                dst[1] = *reinterpret_cast<const float2*>(base + (W_ + col) * C_);
                dst[2] = r2ok
                       ? *reinterpret_cast<const float2*>(base + (2 * W_ + col) * C_)
                       : make_float2(0.f, 0.f);
            } else {                        // right pad column
                dst[0] = make_float2(0.f, 0.f);
                dst[1] = make_float2(0.f, 0.f);
                dst[2] = make_float2(0.f, 0.f);
            }
        };

        float2 c0[3], c1[3], c2[3];
        loadcol(2 * ow0,     c0);
        loadcol(2 * ow0 + 1, c1);
        loadcol(2 * ow0 + 2, c2);

        float* orow = out + ((b * OH_ + oh) * OW_) * C_ + c;

#pragma unroll
        for (int i = 0; i < OW_PER_WARP; ++i) {
            const int ow = ow0 + i;

            // Gather window into sort workspace (renamed away after unroll)
            float2 v[9];
            v[0] = c0[0]; v[1] = c0[1]; v[2] = c0[2];
            v[3] = c1[0]; v[4] = c1[1]; v[5] = c1[2];
            v[6] = c2[0]; v[7] = c2[1]; v[8] = c2[2];

            // Rotate and issue next columns' loads so the sort hides latency.
            c0[0] = c2[0]; c0[1] = c2[1]; c0[2] = c2[2];
            if (i + 1 < OW_PER_WARP) {
                loadcol(2 * ow + 3, c1);
                loadcol(2 * ow + 4, c2);
            }

            // L2 prefetch for the loads TWO iterations out (cols 2ow+5/6),
            // converting their DRAM latency to L2 latency when consumed.
            if (i + 2 < OW_PER_WARP) {
                const int pc = 2 * ow + 5;   // and pc+1
                if (pc + 1 < W_) {
                    l2_prefetch(base + pc * C_);
                    l2_prefetch(base + (pc + 1) * C_);
                    l2_prefetch(base + (W_ + pc) * C_);
                    l2_prefetch(base + (W_ + pc + 1) * C_);
                    if (r2ok) {
                        l2_prefetch(base + (2 * W_ + pc) * C_);
                        l2_prefetch(base + (2 * W_ + pc + 1) * C_);
                    }
                }
            }

            // Optimal 9-input sorting network: 25 CEs, depth 7 (descending).
            // 5 CEs on the fma pipe (CEF) — empirical optimum from R4/R5.
            CEF(0,3) CEF(1,7) CEF(2,5) CEF(4,8)
            CE(0,7) CE(2,4) CE(3,8) CEF(5,6)
            CE(0,2) CE(1,3) CE(4,5) CE(7,8)
            CE(1,4) CE(3,6) CE(5,7)
            CE(0,1) CE(2,4) CE(3,5) CE(6,8)
            CE(2,3) CE(4,5) CE(6,7)
            CE(1,2) CE(3,4) CE(5,6)

            // Rank-weighted sum (v[0] is the max, matching -sort(-p))
            float accx = v[0].x * wgt[0].x;
            float accy = v[0].y * wgt[0].y;
#pragma unroll
            for (int k = 1; k < 9; k++) {
                accx = fmaf(v[k].x, wgt[k].x, accx);
                accy = fmaf(v[k].y, wgt[k].y, accy);
            }

            *reinterpret_cast<float2*>(orow + ow * C_) = make_float2(accx, accy);
        }
    }
}

extern "C" void kernel_launch(void* const* d_in, const int* in_sizes, int n_in,
                              void* d_out, int out_size)
{
    const float* in = (const float*)d_in[0];   // (16,224,224,64)
    const float* kw = (const float*)d_in[1];   // (9,64)
    float* out = (float*)d_out;                // (16,112,112,64)

    dim3 grid(OH_ / ROWS_PER_CTA, B_);
    dim3 block(256);
    owa_pool_kernel<<<grid, block>>>(in, kw, out);
}

// round 8
// speedup vs baseline: 1.0804x; 1.0804x over previous
#include <cuda_runtime.h>

// OWA pooling: 3x3 window, stride 2, SAME pad (0 top/left, 1 bottom/right),
// sort window descending, dot with per-channel rank weights.
// inputs: (16,224,224,64) f32 NHWC ; kernel: (9,64) f32 ; out: (16,112,112,64) f32

#define B_  16
#define H_  224
#define W_  224
#define C_  64
#define OH_ 112
#define OW_ 112
#define OW_PER_WARP 14   // 112 / 8 warps

// Descending compare-exchange, FMNMX form (alu pipe): 4 ops per float2
#define CE(i, j)                                          \
    {                                                     \
        float tx = fmaxf(v[i].x, v[j].x);                 \
        float ty = fmaxf(v[i].y, v[j].y);                 \
        v[j].x = fminf(v[i].x, v[j].x);                   \
        v[j].y = fminf(v[i].y, v[j].y);                   \
        v[i].x = tx;                                      \
        v[i].y = ty;                                      \
    }

// Descending compare-exchange, arithmetic form (fma pipe):
// max = 0.5*((a+b)+|a-b|), min = 0.5*((a+b)-|a-b|).
#define CEF(i, j)                                         \
    {                                                     \
        float sx = v[i].x + v[j].x;                       \
        float dx = v[i].x - v[j].x;                       \
        float sy = v[i].y + v[j].y;                       \
        float dy = v[i].y - v[j].y;                       \
        float mxx = sx + fabsf(dx);                       \
        float mnx = sx - fabsf(dx);                       \
        float mxy = sy + fabsf(dy);                       \
        float mny = sy - fabsf(dy);                       \
        v[i].x = 0.5f * mxx;                              \
        v[j].x = 0.5f * mnx;                              \
        v[i].y = 0.5f * mxy;                              \
        v[j].y = 0.5f * mny;                              \
    }

__global__ __launch_bounds__(256, 4) void owa_pool_kernel(
    const float* __restrict__ in,   // (B,H,W,C)
    const float* __restrict__ kw,   // (9,C)
    float* __restrict__ out)        // (B,OH,OW,C)
{
    // Per-rank weights live in shared memory instead of 18 pinned registers:
    // frees registers for a 4th resident CTA while the load pipeline stays intact.
    __shared__ float2 swgt[9][32];   // [rank][lane] -> that lane's channel pair

    const int oh   = blockIdx.x;
    const int b    = blockIdx.y;
    const int warp = threadIdx.x >> 5;
    const int lane = threadIdx.x & 31;
    const int c    = lane * 2;          // this thread's channel pair

    // Cooperative one-time weight stage: 288 slots, 256 threads -> strided loop.
    for (int idx = threadIdx.x; idx < 9 * 32; idx += 256) {
        const int k = idx >> 5;       // rank
        const int l = idx & 31;       // lane slot
        swgt[k][l] = *reinterpret_cast<const float2*>(kw + k * C_ + l * 2);
    }
    __syncthreads();

    const int r0 = oh * 2;
    const bool r2ok = (r0 + 2 < H_);    // bottom pad row when oh == 111
    const float* base = in + ((b * H_ + r0) * W_) * C_ + c;

    // Load one input column (3 rows) of this channel pair; zeros for pad.
    auto loadcol = [&](int col, float2* dst) {
        if (col < W_) {
            dst[0] = *reinterpret_cast<const float2*>(base + col * C_);
            dst[1] = *reinterpret_cast<const float2*>(base + (W_ + col) * C_);
            dst[2] = r2ok
                   ? *reinterpret_cast<const float2*>(base + (2 * W_ + col) * C_)
                   : make_float2(0.f, 0.f);
        } else {                        // right pad column
            dst[0] = make_float2(0.f, 0.f);
            dst[1] = make_float2(0.f, 0.f);
            dst[2] = make_float2(0.f, 0.f);
        }
    };

    const int ow0 = warp * OW_PER_WARP;

    float2 c0[3], c1[3], c2[3];
    loadcol(2 * ow0,     c0);
    loadcol(2 * ow0 + 1, c1);
    loadcol(2 * ow0 + 2, c2);

    float* orow = out + ((b * OH_ + oh) * OW_) * C_ + c;

    // Fully unrolled: rotation/gather copies become register renames,
    // loop overhead disappears, ptxas schedules loads globally.
#pragma unroll
    for (int i = 0; i < OW_PER_WARP; ++i) {
        const int ow = ow0 + i;

        // Gather window into sort workspace (renamed away after unroll)
        float2 v[9];
        v[0] = c0[0]; v[1] = c0[1]; v[2] = c0[2];
        v[3] = c1[0]; v[4] = c1[1]; v[5] = c1[2];
        v[6] = c2[0]; v[7] = c2[1]; v[8] = c2[2];

        // Rotate and issue next columns' loads so the sort hides latency.
        c0[0] = c2[0]; c0[1] = c2[1]; c0[2] = c2[2];
        if (i + 1 < OW_PER_WARP) {
            loadcol(2 * ow + 3, c1);
            loadcol(2 * ow + 4, c2);
        }

        // Optimal 9-input sorting network: 25 CEs, depth 7 (descending).
        // 5 CEs on the fma pipe (CEF) — empirical optimum from R4/R5.
        CEF(0,3) CEF(1,7) CEF(2,5) CEF(4,8)
        CE(0,7) CE(2,4) CE(3,8) CEF(5,6)
        CE(0,2) CE(1,3) CE(4,5) CE(7,8)
        CE(1,4) CE(3,6) CE(5,7)
        CE(0,1) CE(2,4) CE(3,5) CE(6,8)
        CE(2,3) CE(4,5) CE(6,7)
        CE(1,2) CE(3,4) CE(5,6)

        // Rank-weighted sum; weights streamed from shared memory (LDS.64,
        // conflict-free: lane l reads swgt[k][l], 8B stride across lanes).
        float2 w0 = swgt[0][lane];
        float accx = v[0].x * w0.x;
        float accy = v[0].y * w0.y;
#pragma unroll
        for (int k = 1; k < 9; k++) {
            float2 wk = swgt[k][lane];
            accx = fmaf(v[k].x, wk.x, accx);
            accy = fmaf(v[k].y, wk.y, accy);
        }

        *reinterpret_cast<float2*>(orow + ow * C_) = make_float2(accx, accy);
    }
}

extern "C" void kernel_launch(void* const* d_in, const int* in_sizes, int n_in,
                              void* d_out, int out_size)
{
    const float* in = (const float*)d_in[0];   // (16,224,224,64)
    const float* kw = (const float*)d_in[1];   // (9,64)
    float* out = (float*)d_out;                // (16,112,112,64)

    dim3 grid(OH_, B_);
    dim3 block(256);
    owa_pool_kernel<<<grid, block>>>(in, kw, out);
}